// round 15
// baseline (speedup 1.0000x reference)
#include <cuda_runtime.h>
#include <cuda_fp16.h>
#include <cstdint>

#define FULL 0xFFFFFFFFu
constexpr int Bb = 512;
constexpr float ALPHA = 0.2f;

// ---------------- mma / ldmatrix helpers (baseline PTX, sm_80+) ----------------
__device__ __forceinline__ void mma16816(float* d, const uint32_t* a, const uint32_t* b) {
    asm volatile("mma.sync.aligned.m16n8k16.row.col.f32.f16.f16.f32 "
        "{%0,%1,%2,%3}, {%4,%5,%6,%7}, {%8,%9}, {%0,%1,%2,%3};"
        : "+f"(d[0]), "+f"(d[1]), "+f"(d[2]), "+f"(d[3])
        : "r"(a[0]), "r"(a[1]), "r"(a[2]), "r"(a[3]), "r"(b[0]), "r"(b[1]));
}
__device__ __forceinline__ void ldm_x4(uint32_t* r, uint32_t addr) {
    asm volatile("ldmatrix.sync.aligned.m8n8.x4.shared.b16 {%0,%1,%2,%3}, [%4];"
        : "=r"(r[0]), "=r"(r[1]), "=r"(r[2]), "=r"(r[3]) : "r"(addr));
}
__device__ __forceinline__ void ldm_x4t(uint32_t* r, uint32_t addr) {
    asm volatile("ldmatrix.sync.aligned.m8n8.x4.trans.shared.b16 {%0,%1,%2,%3}, [%4];"
        : "=r"(r[0]), "=r"(r[1]), "=r"(r[2]), "=r"(r[3]) : "r"(addr));
}
__device__ __forceinline__ void ldm_x2t(uint32_t* r, uint32_t addr) {
    asm volatile("ldmatrix.sync.aligned.m8n8.x2.trans.shared.b16 {%0,%1}, [%2];"
        : "=r"(r[0]), "=r"(r[1]) : "r"(addr));
}
__device__ __forceinline__ uint32_t smem_u32(const void* p) {
    uint32_t a;
    asm("{ .reg .u64 t; cvta.to.shared.u64 t, %1; cvt.u32.u64 %0, t; }" : "=r"(a) : "l"(p));
    return a;
}

#define RADD(v) { _Pragma("unroll") for (int _o = 16; _o; _o >>= 1) v += __shfl_xor_sync(FULL, v, _o); }

// ---------------- precomputed globals ----------------
// g_u: 0=u1a 1=u2a 2=u3a 3=u1b 4=u2b 5=u3g
__device__ float g_u[6][128];
__device__ float g_c1[2];
// g2w as fp16 [128][136] (row=k, col=d), 34816 bytes
__device__ __align__(16) uint8_t g_w2img[34816];

// ONE setup kernel. grid 384 x 128 threads:
//   blocks 0..255  : (layer = b>>7, k = b&127) -> u1,u2,u3a + c1
//   blocks 256..383: k = b-256 -> g2w fp16 image row k + u3g[k]
__global__ void setup_kernel(
    const float* __restrict__ w2a, const float* __restrict__ w3a,
    const float* __restrict__ qa,  const float* __restrict__ aa,
    const float* __restrict__ a2a,
    const float* __restrict__ w2b, const float* __restrict__ w3b,
    const float* __restrict__ qb,  const float* __restrict__ ab,
    const float* __restrict__ a2b,
    const float* __restrict__ g2w)
{
    const int bid = blockIdx.x;
    const int c   = threadIdx.x;
    const int wp  = c >> 5, ln = c & 31;

    if (bid < 256) {
        const int layer = bid >> 7;
        const int k     = bid & 127;
        const float* w2 = layer ? w2b : w2a;
        const float* w3 = layer ? w3b : w3a;
        const float* q  = layer ? qb  : qa;
        const float* a  = layer ? ab  : aa;
        const float* a2 = layer ? a2b : a2a;

        float w2v = w2[k * 128 + c];
        float p1 = w2v * a[128 + c];
        float p2 = w2v * a2[c];
        // u3 only needed for layer 0 (layer1's u3 is folded into u3g blocks)
        float p3 = (layer == 0) ? w3[k * 128 + c] * a2[128 + c] : 0.f;
        float p4 = (k == 0) ? q[c] * a[c] : 0.f;
        RADD(p1); RADD(p2); RADD(p3); RADD(p4);
        __shared__ float sh[4][4];
        if (ln == 0) { sh[0][wp] = p1; sh[1][wp] = p2; sh[2][wp] = p3; sh[3][wp] = p4; }
        __syncthreads();
        if (c == 0) {
            float u1 = sh[0][0] + sh[0][1] + sh[0][2] + sh[0][3];
            float u2 = sh[1][0] + sh[1][1] + sh[1][2] + sh[1][3];
            if (layer == 0) {
                g_u[0][k] = u1; g_u[1][k] = u2;
                g_u[2][k] = sh[2][0] + sh[2][1] + sh[2][2] + sh[2][3];
            } else {
                g_u[3][k] = u1; g_u[4][k] = u2;
            }
            if (k == 0) g_c1[layer] = sh[3][0] + sh[3][1] + sh[3][2] + sh[3][3];
        }
    } else {
        const int k = bid - 256;
        // fp16 image of g2w row k
        float gkc = g2w[k * 128 + c];
        *(__half*)(g_w2img + (k * 136 + c) * 2) = __float2half(gkc);
        // t(c) = sum_n g2w[k,n] * w3b[n,c]  (g2w broadcast, w3b coalesced)
        float t = 0.f;
        #pragma unroll 4
        for (int n = 0; n < 128; n += 4) {
            float4 g = *(const float4*)(g2w + k * 128 + n);
            t += g.x * w3b[n * 128 + c];
            t += g.y * w3b[(n + 1) * 128 + c];
            t += g.z * w3b[(n + 2) * 128 + c];
            t += g.w * w3b[(n + 3) * 128 + c];
        }
        float p5 = t * a2b[128 + c];
        RADD(p5);
        __shared__ float sh5[4];
        if (ln == 0) sh5[wp] = p5;
        __syncthreads();
        if (c == 0) g_u[5][k] = sh5[0] + sh5[1] + sh5[2] + sh5[3];
    }
}

// ---------------- smem layout (bytes), all matrices single fp16 ----------------
constexpr int SM_ATT1  = 0;        // [128][72] = 18432
constexpr int SM_ATTN  = 18432;    // [64][136] = 17408
constexpr int SM_G2W   = 0;        // 34816 (overlaps ATT1+ATTN; layer1 after P1)
constexpr int SM_X     = 35840;    // [64][136] : x0, then y (layer1)
constexpr int SM_Y     = 53248;    // [64][136] : x1
constexpr int SM_P     = 70656;    // [64][72] = 9216
constexpr int SM_RESID = 79872;    // fp32 [64][128] = 32768
constexpr int SM_E1V   = 112640;
constexpr int SM_S2    = 112896;
constexpr int SM_VV    = 113152;
constexpr int SM_DXA   = 113408;
constexpr int SM_DXB   = 113664;
constexpr int SM_DXC   = 113920;
constexpr int SM_F2    = 114176;   // 128 f
constexpr int SM_DEA   = 114688;
constexpr int SM_DEB   = 115200;
constexpr int SM_DEC   = 115712;
constexpr int SM_EMASK = 116224;   // 128 u64
constexpr int SM_NMASK = 117248;   // 64 x 2 u64
constexpr int SMEM_BYTES = 118272;

__device__ __forceinline__ void sth1(uint8_t* sm, int off, float a) {
    *(__half*)(sm + off) = __float2half(a);
}
__device__ __forceinline__ void sth2(uint8_t* sm, int off, float a, float b) {
    *(__half2*)(sm + off) = __floats2half2_rn(a, b);
}

__global__ __launch_bounds__(1024, 1) void session_kernel(
    const int*   __restrict__ inputs,
    const float* __restrict__ HT,
    const float* __restrict__ emb,
    const float* __restrict__ emb2,
    float*       __restrict__ out)
{
    extern __shared__ __align__(16) uint8_t sm[];
    const int tid  = threadIdx.x;
    const int warp = tid >> 5;
    const int lane = tid & 31;
    const int b    = blockIdx.x;
    const size_t BLD = (size_t)Bb * 64 * 128;
    uint32_t sbase = smem_u32(sm);

    float* e1v = (float*)(sm + SM_E1V);
    float* s2v = (float*)(sm + SM_S2);
    float* vv  = (float*)(sm + SM_VV);
    float* dxa = (float*)(sm + SM_DXA);
    float* dxb = (float*)(sm + SM_DXB);
    float* dxc = (float*)(sm + SM_DXC);
    float* f2  = (float*)(sm + SM_F2);
    float* dea = (float*)(sm + SM_DEA);
    float* deb = (float*)(sm + SM_DEB);
    float* dec = (float*)(sm + SM_DEC);
    unsigned long long* emask = (unsigned long long*)(sm + SM_EMASK);
    unsigned long long* nmask = (unsigned long long*)(sm + SM_NMASK);
    float* resid = (float*)(sm + SM_RESID);

    // ---- Phase 0: gathers, x0 fp16 image, 6-channel dots, masks ----
    #pragma unroll
    for (int it = 0; it < 2; it++) {
        int j = warp + 32 * it;
        int tok = inputs[b * 64 + j];
        float4 v = ((const float4*)(emb + (size_t)tok * 128))[lane];
        ((float4*)resid)[j * 32 + lane] = v;
        float4 v2 = ((const float4*)(emb2 + (size_t)tok * 128))[lane];
        ((float4*)(out + 2 * BLD + ((size_t)b * 64 + j) * 128))[lane] = v2;
        sth2(sm, SM_X + j * 272 + 8 * lane, v.x, v.y);
        sth2(sm, SM_X + j * 272 + 8 * lane + 4, v.z, v.w);
        float p[6];
        #pragma unroll
        for (int c = 0; c < 6; c++) {
            float4 gu = ((const float4*)g_u[c])[lane];
            p[c] = v.x * gu.x + v.y * gu.y + v.z * gu.z + v.w * gu.w;
        }
        #pragma unroll
        for (int c = 0; c < 6; c++) RADD(p[c]);
        if (lane == 0) {
            float e = g_c1[0] + p[0];
            e1v[j] = e > 0.f ? e : ALPHA * e;
            s2v[j] = p[1]; vv[j] = p[2];
            dxa[j] = p[3]; dxb[j] = p[4]; dxc[j] = p[5];
        }
    }
    #pragma unroll
    for (int it = 0; it < 4; it++) {
        int e = warp + 32 * it;
        const float* row = HT + ((size_t)b * 128 + e) * 64;
        unsigned lo = __ballot_sync(FULL, row[lane] > 0.f);
        unsigned hi = __ballot_sync(FULL, row[lane + 32] > 0.f);
        if (lane == 0) emask[e] = (unsigned long long)lo | ((unsigned long long)hi << 32);
    }
    __syncthreads();
    // nmask via ballot-transpose
    {
        unsigned long long eA = emask[lane],      eB = emask[lane + 32];
        unsigned long long eC = emask[lane + 64], eD = emask[lane + 96];
        #pragma unroll
        for (int t = 0; t < 2; t++) {
            int j = warp + 32 * t;
            unsigned b0 = __ballot_sync(FULL, (eA >> j) & 1ull);
            unsigned b1 = __ballot_sync(FULL, (eB >> j) & 1ull);
            unsigned b2 = __ballot_sync(FULL, (eC >> j) & 1ull);
            unsigned b3 = __ballot_sync(FULL, (eD >> j) & 1ull);
            if (lane == 0) {
                nmask[2 * j]     = (unsigned long long)b0 | ((unsigned long long)b1 << 32);
                nmask[2 * j + 1] = (unsigned long long)b2 | ((unsigned long long)b3 << 32);
            }
        }
    }
    __syncthreads();

    for (int layer = 0; layer < 2; layer++) {
        // ---- att1[e][j] softmax: hoisted exps, unrolled iterations ----
        {
            float ex0 = __expf(e1v[lane]), ex32 = __expf(e1v[lane + 32]);
            float vv0 = vv[lane], vv32 = vv[lane + 32];
            float da0 = 0.f, da32 = 0.f, db0 = 0.f, db32 = 0.f, dc0 = 0.f, dc32 = 0.f;
            if (layer == 0) {
                da0 = dxa[lane]; da32 = dxa[lane + 32];
                db0 = dxb[lane]; db32 = dxb[lane + 32];
                dc0 = dxc[lane]; dc32 = dxc[lane + 32];
            }
            #pragma unroll
            for (int it = 0; it < 4; it++) {
                int e = warp + 32 * it;
                unsigned long long m = emask[e];
                bool b0 = (m >> lane) & 1ull, b1 = (m >> (lane + 32)) & 1ull;
                float w0 = (m == 0ull) ? (1.f / 64.f) : (b0 ? ex0 : 0.f);
                float w1 = (m == 0ull) ? (1.f / 64.f) : (b1 ? ex32 : 0.f);
                float s = w0 + w1;
                float t = w0 * vv0 + w1 * vv32;
                float ta = 0.f, tb = 0.f, tc = 0.f;
                if (layer == 0) {
                    ta = w0 * da0 + w1 * da32;
                    tb = w0 * db0 + w1 * db32;
                    tc = w0 * dc0 + w1 * dc32;
                }
                RADD(s); RADD(t);
                if (layer == 0) { RADD(ta); RADD(tb); RADD(tc); }
                float inv = 1.f / s;
                w0 *= inv; w1 *= inv;
                if (lane == 0) {
                    f2[e] = t * inv;
                    if (layer == 0) { dea[e] = ta * inv; deb[e] = tb * inv; dec[e] = tc * inv; }
                }
                sth1(sm, SM_ATT1 + e * 144 + lane * 2, w0);
                sth1(sm, SM_ATT1 + e * 144 + (lane + 32) * 2, w1);
            }
        }
        __syncthreads();

        // ---- attN[j][e] softmax via factored exp; de* read from smem ----
        {
            float f2l[4], efv[4], ef02v[4];
            #pragma unroll
            for (int t = 0; t < 4; t++) {
                float f = f2[lane + 32 * t];
                f2l[t] = f;
                efv[t] = __expf(f);
                ef02v[t] = __expf(ALPHA * f);
            }
            #pragma unroll
            for (int it = 0; it < 2; it++) {
                int j = warp + 32 * it;
                unsigned long long m0 = nmask[2 * j], m1 = nmask[2 * j + 1];
                float ss = s2v[j];
                float esj = __expf(ss), es02j = __expf(ALPHA * ss);
                bool empty = (m0 | m1) == 0ull;
                bool bt[4] = { (bool)((m0 >> lane) & 1ull), (bool)((m0 >> (lane + 32)) & 1ull),
                               (bool)((m1 >> lane) & 1ull), (bool)((m1 >> (lane + 32)) & 1ull) };
                float w[4];
                float s = 0.f;
                #pragma unroll
                for (int t = 0; t < 4; t++) {
                    float val = (ss + f2l[t] > 0.f) ? esj * efv[t] : es02j * ef02v[t];
                    w[t] = empty ? (1.f / 128.f) : (bt[t] ? val : 0.f);
                    s += w[t];
                }
                float ta = 0.f, tb = 0.f, tc = 0.f;
                if (layer == 0) {
                    #pragma unroll
                    for (int t = 0; t < 4; t++) {
                        ta += w[t] * dea[lane + 32 * t];
                        tb += w[t] * deb[lane + 32 * t];
                        tc += w[t] * dec[lane + 32 * t];
                    }
                }
                RADD(s);
                if (layer == 0) { RADD(ta); RADD(tb); RADD(tc); }
                float inv = 1.f / s;
                #pragma unroll
                for (int t = 0; t < 4; t++) w[t] *= inv;
                if (layer == 0 && lane == 0) {
                    float x1a = g_c1[1] + ta * inv + dxa[j];
                    e1v[j] = x1a > 0.f ? x1a : ALPHA * x1a;
                    s2v[j] = tb * inv + dxb[j];
                    vv[j]  = tc * inv + dxc[j];
                }
                #pragma unroll
                for (int t = 0; t < 4; t++)
                    sth1(sm, SM_ATTN + j * 272 + (lane + 32 * t) * 2, w[t]);
            }
        }
        __syncthreads();

        // ---- P = attN @ att1 : M64 K128 N64, single fp16 MMA ----
        {
            int mt = warp >> 3, nt = warp & 7;
            float d[4] = {0.f, 0.f, 0.f, 0.f};
            uint32_t aA = sbase + SM_ATTN + (mt * 16 + (lane & 15)) * 272 + (lane >> 4) * 16;
            uint32_t bA = sbase + SM_ATT1 + (lane & 15) * 144 + nt * 16;
            #pragma unroll
            for (int k = 0; k < 8; k++) {
                uint32_t a[4], bf[2];
                ldm_x4(a, aA + k * 32);
                ldm_x2t(bf, bA + k * 2304);
                mma16816(d, a, bf);
            }
            int r = mt * 16 + (lane >> 2), c = nt * 8 + (lane & 3) * 2;
            sth2(sm, SM_P + r * 144 + c * 2, d[0], d[1]);
            sth2(sm, SM_P + (r + 8) * 144 + c * 2, d[2], d[3]);
        }
        __syncthreads();

        if (layer == 0) {
            // ---- node0 = P @ x0 ; +resid -> x1 into SM_Y ----
            int mt = warp >> 3, nc = warp & 7;
            float d[8] = {0.f, 0.f, 0.f, 0.f, 0.f, 0.f, 0.f, 0.f};
            uint32_t aA = sbase + SM_P + (mt * 16 + (lane & 15)) * 144 + (lane >> 4) * 16;
            uint32_t bA = sbase + SM_X + (lane & 15) * 272 + nc * 32 + (lane >> 4) * 16;
            #pragma unroll
            for (int k = 0; k < 4; k++) {
                uint32_t a[4], bf[4];
                ldm_x4(a, aA + k * 32);
                ldm_x4t(bf, bA + k * 4352);
                mma16816(d, a, bf);
                mma16816(d + 4, a, bf + 2);
            }
            int r = mt * 16 + (lane >> 2);
            #pragma unroll
            for (int t = 0; t < 2; t++) {
                int c = nc * 16 + t * 8 + (lane & 3) * 2;
                sth2(sm, SM_Y + r * 272 + c * 2,
                     d[t*4+0] + resid[r * 128 + c], d[t*4+1] + resid[r * 128 + c + 1]);
                sth2(sm, SM_Y + (r + 8) * 272 + c * 2,
                     d[t*4+2] + resid[(r + 8) * 128 + c], d[t*4+3] + resid[(r + 8) * 128 + c + 1]);
            }
            __syncthreads();
        } else {
            // ---- FUSED: copy g2w fp16 image -> base 0, AND y = P1 @ x1 -> SM_X ----
            {
                const float4* src = (const float4*)g_w2img;
                float4* dst = (float4*)(sm + SM_G2W);
                for (int i = tid; i < 2176; i += 1024) dst[i] = src[i];
            }
            {
                int mt = warp >> 3, nc = warp & 7;
                float d[8] = {0.f, 0.f, 0.f, 0.f, 0.f, 0.f, 0.f, 0.f};
                uint32_t aA = sbase + SM_P + (mt * 16 + (lane & 15)) * 144 + (lane >> 4) * 16;
                uint32_t bA = sbase + SM_Y + (lane & 15) * 272 + nc * 32 + (lane >> 4) * 16;
                #pragma unroll
                for (int k = 0; k < 4; k++) {
                    uint32_t a[4], bf[4];
                    ldm_x4(a, aA + k * 32);
                    ldm_x4t(bf, bA + k * 4352);
                    mma16816(d, a, bf);
                    mma16816(d + 4, a, bf + 2);
                }
                int r = mt * 16 + (lane >> 2);
                #pragma unroll
                for (int t = 0; t < 2; t++) {
                    int c = nc * 16 + t * 8 + (lane & 3) * 2;
                    sth2(sm, SM_X + r * 272 + c * 2, d[t*4+0], d[t*4+1]);
                    sth2(sm, SM_X + (r + 8) * 272 + c * 2, d[t*4+2], d[t*4+3]);
                }
            }
            __syncthreads();
            // ---- node1 = y @ g2w ; epilogue writes out directly (+resid) ----
            {
                int mt = warp >> 3, nc = warp & 7;
                float d[8] = {0.f, 0.f, 0.f, 0.f, 0.f, 0.f, 0.f, 0.f};
                uint32_t aA = sbase + SM_X + (mt * 16 + (lane & 15)) * 272 + (lane >> 4) * 16;
                uint32_t bA = sbase + SM_G2W + (lane & 15) * 272 + nc * 32 + (lane >> 4) * 16;
                #pragma unroll
                for (int k = 0; k < 8; k++) {
                    uint32_t a[4], bf[4];
                    ldm_x4(a, aA + k * 32);
                    ldm_x4t(bf, bA + k * 4352);
                    mma16816(d, a, bf);
                    mma16816(d + 4, a, bf + 2);
                }
                int r = mt * 16 + (lane >> 2);
                #pragma unroll
                for (int t = 0; t < 2; t++) {
                    int c = nc * 16 + t * 8 + (lane & 3) * 2;
                    float2 v0 = make_float2(d[t*4+0] + resid[r * 128 + c],
                                            d[t*4+1] + resid[r * 128 + c + 1]);
                    float2 v1 = make_float2(d[t*4+2] + resid[(r + 8) * 128 + c],
                                            d[t*4+3] + resid[(r + 8) * 128 + c + 1]);
                    size_t o0 = ((size_t)b * 64 + r) * 128 + c;
                    size_t o1 = ((size_t)b * 64 + r + 8) * 128 + c;
                    *(float2*)(out + o0) = v0;
                    *(float2*)(out + BLD + o0) = v0;
                    *(float2*)(out + o1) = v1;
                    *(float2*)(out + BLD + o1) = v1;
                }
            }
        }
    }
}

extern "C" void kernel_launch(void* const* d_in, const int* in_sizes, int n_in,
                              void* d_out, int out_size)
{
    const int*   inputs = (const int*)d_in[0];
    const float* HT     = (const float*)d_in[1];
    const float* emb    = (const float*)d_in[4];
    const float* emb2   = (const float*)d_in[5];
    const float* g1_w2  = (const float*)d_in[6];
    const float* g1_w3  = (const float*)d_in[7];
    const float* g1_q   = (const float*)d_in[8];
    const float* g1_a   = (const float*)d_in[9];
    const float* g1_a2  = (const float*)d_in[10];
    const float* g2_w   = (const float*)d_in[11];
    const float* g2_w2  = (const float*)d_in[12];
    const float* g2_w3  = (const float*)d_in[13];
    const float* g2_q   = (const float*)d_in[14];
    const float* g2_a   = (const float*)d_in[15];
    const float* g2_a2  = (const float*)d_in[16];
    float* out = (float*)d_out;

    cudaFuncSetAttribute(session_kernel,
                         cudaFuncAttributeMaxDynamicSharedMemorySize, SMEM_BYTES);

    setup_kernel<<<384, 128>>>(g1_w2, g1_w3, g1_q, g1_a, g1_a2,
                               g2_w2, g2_w3, g2_q, g2_a, g2_a2, g2_w);
    session_kernel<<<Bb, 1024, SMEM_BYTES>>>(inputs, HT, emb, emb2, out);
}

// round 16
// speedup vs baseline: 1.1051x; 1.1051x over previous
#include <cuda_runtime.h>
#include <cuda_fp16.h>
#include <cstdint>

#define FULL 0xFFFFFFFFu
constexpr int Bb = 512;
constexpr float ALPHA = 0.2f;

// ---------------- mma / ldmatrix helpers ----------------
__device__ __forceinline__ void mma16816(float* d, const uint32_t* a, const uint32_t* b) {
    asm volatile("mma.sync.aligned.m16n8k16.row.col.f32.f16.f16.f32 "
        "{%0,%1,%2,%3}, {%4,%5,%6,%7}, {%8,%9}, {%0,%1,%2,%3};"
        : "+f"(d[0]), "+f"(d[1]), "+f"(d[2]), "+f"(d[3])
        : "r"(a[0]), "r"(a[1]), "r"(a[2]), "r"(a[3]), "r"(b[0]), "r"(b[1]));
}
__device__ __forceinline__ void ldm_x4(uint32_t* r, uint32_t addr) {
    asm volatile("ldmatrix.sync.aligned.m8n8.x4.shared.b16 {%0,%1,%2,%3}, [%4];"
        : "=r"(r[0]), "=r"(r[1]), "=r"(r[2]), "=r"(r[3]) : "r"(addr));
}
__device__ __forceinline__ void ldm_x4t(uint32_t* r, uint32_t addr) {
    asm volatile("ldmatrix.sync.aligned.m8n8.x4.trans.shared.b16 {%0,%1,%2,%3}, [%4];"
        : "=r"(r[0]), "=r"(r[1]), "=r"(r[2]), "=r"(r[3]) : "r"(addr));
}
__device__ __forceinline__ void ldm_x2t(uint32_t* r, uint32_t addr) {
    asm volatile("ldmatrix.sync.aligned.m8n8.x2.trans.shared.b16 {%0,%1}, [%2];"
        : "=r"(r[0]), "=r"(r[1]) : "r"(addr));
}
__device__ __forceinline__ uint32_t smem_u32(const void* p) {
    uint32_t a;
    asm("{ .reg .u64 t; cvta.to.shared.u64 t, %1; cvt.u32.u64 %0, t; }" : "=r"(a) : "l"(p));
    return a;
}

#define RADD(v) { _Pragma("unroll") for (int _o = 16; _o; _o >>= 1) v += __shfl_xor_sync(FULL, v, _o); }

// ---------------- precomputed globals ----------------
__device__ float g_u[6][128];
__device__ float g_u3b[128];
__device__ float g_c1[2];
__device__ __align__(16) uint8_t g_w2img[34816];  // fp16 g2w [128][136]

// grid (2, 128) x 128 threads  (R11/R14 shape — measured fastest)
__global__ void precompute_kernel(
    const float* __restrict__ w2a, const float* __restrict__ w3a,
    const float* __restrict__ qa,  const float* __restrict__ aa,
    const float* __restrict__ a2a,
    const float* __restrict__ w2b, const float* __restrict__ w3b,
    const float* __restrict__ qb,  const float* __restrict__ ab,
    const float* __restrict__ a2b)
{
    const int layer = blockIdx.x;
    const int k     = blockIdx.y;
    const int c     = threadIdx.x;
    const int wp    = c >> 5, ln = c & 31;
    const float* w2 = layer ? w2b : w2a;
    const float* w3 = layer ? w3b : w3a;
    const float* q  = layer ? qb  : qa;
    const float* a  = layer ? ab  : aa;
    const float* a2 = layer ? a2b : a2a;

    float w2v = w2[k * 128 + c];
    float p1 = w2v * a[128 + c];
    float p2 = w2v * a2[c];
    float p3 = w3[k * 128 + c] * a2[128 + c];
    float p4 = (k == 0) ? q[c] * a[c] : 0.f;
    RADD(p1); RADD(p2); RADD(p3); RADD(p4);
    __shared__ float sh[4][4];
    if (ln == 0) { sh[0][wp] = p1; sh[1][wp] = p2; sh[2][wp] = p3; sh[3][wp] = p4; }
    __syncthreads();
    if (c == 0) {
        float u1 = sh[0][0] + sh[0][1] + sh[0][2] + sh[0][3];
        float u2 = sh[1][0] + sh[1][1] + sh[1][2] + sh[1][3];
        float u3 = sh[2][0] + sh[2][1] + sh[2][2] + sh[2][3];
        if (layer == 0) { g_u[0][k] = u1; g_u[1][k] = u2; g_u[2][k] = u3; }
        else            { g_u[3][k] = u1; g_u[4][k] = u2; g_u3b[k] = u3; }
        if (k == 0) g_c1[layer] = sh[3][0] + sh[3][1] + sh[3][2] + sh[3][3];
    }
}

// 64 blocks x 256: g2w -> fp16 image; warps 0..127 also compute u3g
__global__ void img_kernel(const float* __restrict__ g2w) {
    int idx = blockIdx.x * 256 + threadIdx.x;
    int kk = idx >> 7, d = idx & 127;
    *(__half*)(g_w2img + (kk * 136 + d) * 2) = __float2half(g2w[kk * 128 + d]);
    int gw = blockIdx.x * 8 + (threadIdx.x >> 5);
    if (gw < 128) {
        int ln = threadIdx.x & 31;
        float s = 0.f;
        #pragma unroll
        for (int t = 0; t < 4; t++)
            s += g2w[gw * 128 + ln + 32 * t] * g_u3b[ln + 32 * t];
        RADD(s);
        if (ln == 0) g_u[5][gw] = s;
    }
}

// ---------------- smem layout (bytes) ----------------
constexpr int SM_ATT1  = 0;        // [128][72] = 18432
constexpr int SM_ATTN  = 18432;    // [64][136] = 17408
constexpr int SM_G2W   = 0;        // 34816 overlay
constexpr int SM_X     = 35840;    // [64][136]
constexpr int SM_Y     = 53248;    // [64][136]
constexpr int SM_P     = 70656;    // [64][72] = 9216
constexpr int SM_RESID = 79872;    // fp32 [64][128]
constexpr int SM_E1V   = 112640;
constexpr int SM_S2    = 112896;
constexpr int SM_VV    = 113152;
constexpr int SM_DXA   = 113408;
constexpr int SM_DXB   = 113664;
constexpr int SM_DXC   = 113920;
constexpr int SM_F2    = 114176;
constexpr int SM_DEA   = 114688;
constexpr int SM_DEB   = 115200;
constexpr int SM_DEC   = 115712;
constexpr int SM_EMASK = 116224;
constexpr int SM_NMASK = 117248;
constexpr int SMEM_BYTES = 118272;

__device__ __forceinline__ void sth2(uint8_t* sm, int off, float a, float b) {
    *(__half2*)(sm + off) = __floats2half2_rn(a, b);
}

__global__ __launch_bounds__(1024, 1) void session_kernel(
    const int*   __restrict__ inputs,
    const float* __restrict__ HT,
    const float* __restrict__ emb,
    const float* __restrict__ emb2,
    float*       __restrict__ out)
{
    extern __shared__ __align__(16) uint8_t sm[];
    const int tid  = threadIdx.x;
    const int warp = tid >> 5;
    const int lane = tid & 31;
    const int l2   = 2 * lane;
    const int b    = blockIdx.x;
    const size_t BLD = (size_t)Bb * 64 * 128;
    uint32_t sbase = smem_u32(sm);

    float* e1v = (float*)(sm + SM_E1V);
    float* s2v = (float*)(sm + SM_S2);
    float* vv  = (float*)(sm + SM_VV);
    float* dxa = (float*)(sm + SM_DXA);
    float* dxb = (float*)(sm + SM_DXB);
    float* dxc = (float*)(sm + SM_DXC);
    float* f2  = (float*)(sm + SM_F2);
    float* dea = (float*)(sm + SM_DEA);
    float* deb = (float*)(sm + SM_DEB);
    float* dec = (float*)(sm + SM_DEC);
    unsigned long long* emask = (unsigned long long*)(sm + SM_EMASK);
    unsigned long long* nmask = (unsigned long long*)(sm + SM_NMASK);
    float* resid = (float*)(sm + SM_RESID);

    // ---- Phase 0: gathers, x0 fp16 image, 6-channel dots, masks ----
    #pragma unroll
    for (int it = 0; it < 2; it++) {
        int j = warp + 32 * it;
        int tok = inputs[b * 64 + j];
        float4 v = ((const float4*)(emb + (size_t)tok * 128))[lane];
        ((float4*)resid)[j * 32 + lane] = v;
        float4 v2 = ((const float4*)(emb2 + (size_t)tok * 128))[lane];
        ((float4*)(out + 2 * BLD + ((size_t)b * 64 + j) * 128))[lane] = v2;
        {
            __half2 h0 = __floats2half2_rn(v.x, v.y);
            __half2 h1 = __floats2half2_rn(v.z, v.w);
            uint2 pk = make_uint2(*(uint32_t*)&h0, *(uint32_t*)&h1);
            *(uint2*)(sm + SM_X + j * 272 + 8 * lane) = pk;
        }
        float p[6];
        #pragma unroll
        for (int c = 0; c < 6; c++) {
            float4 gu = ((const float4*)g_u[c])[lane];
            p[c] = v.x * gu.x + v.y * gu.y + v.z * gu.z + v.w * gu.w;
        }
        #pragma unroll
        for (int c = 0; c < 6; c++) RADD(p[c]);
        if (lane == 0) {
            float e = g_c1[0] + p[0];
            e1v[j] = e > 0.f ? e : ALPHA * e;
            s2v[j] = p[1]; vv[j] = p[2];
            dxa[j] = p[3]; dxb[j] = p[4]; dxc[j] = p[5];
        }
    }
    #pragma unroll
    for (int it = 0; it < 4; it++) {
        int e = warp + 32 * it;
        const float* row = HT + ((size_t)b * 128 + e) * 64;
        unsigned lo = __ballot_sync(FULL, row[lane] > 0.f);
        unsigned hi = __ballot_sync(FULL, row[lane + 32] > 0.f);
        if (lane == 0) emask[e] = (unsigned long long)lo | ((unsigned long long)hi << 32);
    }
    __syncthreads();
    // nmask via ballot-transpose
    {
        unsigned long long eA = emask[lane],      eB = emask[lane + 32];
        unsigned long long eC = emask[lane + 64], eD = emask[lane + 96];
        #pragma unroll
        for (int t = 0; t < 2; t++) {
            int j = warp + 32 * t;
            unsigned b0 = __ballot_sync(FULL, (eA >> j) & 1ull);
            unsigned b1 = __ballot_sync(FULL, (eB >> j) & 1ull);
            unsigned b2 = __ballot_sync(FULL, (eC >> j) & 1ull);
            unsigned b3 = __ballot_sync(FULL, (eD >> j) & 1ull);
            if (lane == 0) {
                nmask[2 * j]     = (unsigned long long)b0 | ((unsigned long long)b1 << 32);
                nmask[2 * j + 1] = (unsigned long long)b2 | ((unsigned long long)b3 << 32);
            }
        }
    }
    __syncthreads();

    for (int layer = 0; layer < 2; layer++) {
        // ---- att1[e][j] softmax: paired lanes (j = 2*lane, 2*lane+1), half2 stores ----
        {
            float ex0 = __expf(e1v[l2]), ex1 = __expf(e1v[l2 + 1]);
            float vv0 = vv[l2], vv1 = vv[l2 + 1];
            float da0 = 0.f, da1 = 0.f, db0 = 0.f, db1 = 0.f, dc0 = 0.f, dc1 = 0.f;
            if (layer == 0) {
                da0 = dxa[l2]; da1 = dxa[l2 + 1];
                db0 = dxb[l2]; db1 = dxb[l2 + 1];
                dc0 = dxc[l2]; dc1 = dxc[l2 + 1];
            }
            #pragma unroll
            for (int it = 0; it < 4; it++) {
                int e = warp + 32 * it;
                unsigned long long m = emask[e];
                bool b0 = (m >> l2) & 1ull, b1 = (m >> (l2 + 1)) & 1ull;
                float w0 = (m == 0ull) ? (1.f / 64.f) : (b0 ? ex0 : 0.f);
                float w1 = (m == 0ull) ? (1.f / 64.f) : (b1 ? ex1 : 0.f);
                float s = w0 + w1;
                float t = w0 * vv0 + w1 * vv1;
                float ta = 0.f, tb = 0.f, tc = 0.f;
                if (layer == 0) {
                    ta = w0 * da0 + w1 * da1;
                    tb = w0 * db0 + w1 * db1;
                    tc = w0 * dc0 + w1 * dc1;
                }
                RADD(s); RADD(t);
                if (layer == 0) { RADD(ta); RADD(tb); RADD(tc); }
                float inv = 1.f / s;
                if (lane == 0) {
                    f2[e] = t * inv;
                    if (layer == 0) { dea[e] = ta * inv; deb[e] = tb * inv; dec[e] = tc * inv; }
                }
                sth2(sm, SM_ATT1 + e * 144 + 4 * lane, w0 * inv, w1 * inv);
            }
        }
        __syncthreads();

        // ---- attN[j][e] softmax: paired lanes (e = 2*lane+{0,1}, 64+2*lane+{0,1}) ----
        {
            float f2l[4], efv[4], ef02v[4];
            #pragma unroll
            for (int t = 0; t < 4; t++) {
                int ei = (t >> 1) * 64 + l2 + (t & 1);
                float f = f2[ei];
                f2l[t] = f;
                efv[t] = __expf(f);
                ef02v[t] = __expf(ALPHA * f);
            }
            #pragma unroll
            for (int it = 0; it < 2; it++) {
                int j = warp + 32 * it;
                unsigned long long m0 = nmask[2 * j], m1 = nmask[2 * j + 1];
                float ss = s2v[j];
                float esj = __expf(ss), es02j = __expf(ALPHA * ss);
                bool empty = (m0 | m1) == 0ull;
                bool bt[4] = { (bool)((m0 >> l2) & 1ull), (bool)((m0 >> (l2 + 1)) & 1ull),
                               (bool)((m1 >> l2) & 1ull), (bool)((m1 >> (l2 + 1)) & 1ull) };
                float w[4];
                float s = 0.f;
                #pragma unroll
                for (int t = 0; t < 4; t++) {
                    float val = (ss + f2l[t] > 0.f) ? esj * efv[t] : es02j * ef02v[t];
                    w[t] = empty ? (1.f / 128.f) : (bt[t] ? val : 0.f);
                    s += w[t];
                }
                float ta = 0.f, tb = 0.f, tc = 0.f;
                if (layer == 0) {
                    #pragma unroll
                    for (int t = 0; t < 4; t++) {
                        int ei = (t >> 1) * 64 + l2 + (t & 1);
                        ta += w[t] * dea[ei];
                        tb += w[t] * deb[ei];
                        tc += w[t] * dec[ei];
                    }
                }
                RADD(s);
                if (layer == 0) { RADD(ta); RADD(tb); RADD(tc); }
                float inv = 1.f / s;
                if (layer == 0 && lane == 0) {
                    float x1a = g_c1[1] + ta * inv + dxa[j];
                    e1v[j] = x1a > 0.f ? x1a : ALPHA * x1a;
                    s2v[j] = tb * inv + dxb[j];
                    vv[j]  = tc * inv + dxc[j];
                }
                sth2(sm, SM_ATTN + j * 272 + 4 * lane, w[0] * inv, w[1] * inv);
                sth2(sm, SM_ATTN + j * 272 + 128 + 4 * lane, w[2] * inv, w[3] * inv);
            }
        }
        __syncthreads();

        // ---- P = attN @ att1 : M64 K128 N64, fp16 MMA ----
        {
            int mt = warp >> 3, nt = warp & 7;
            float d[4] = {0.f, 0.f, 0.f, 0.f};
            uint32_t aA = sbase + SM_ATTN + (mt * 16 + (lane & 15)) * 272 + (lane >> 4) * 16;
            uint32_t bA = sbase + SM_ATT1 + (lane & 15) * 144 + nt * 16;
            #pragma unroll
            for (int k = 0; k < 8; k++) {
                uint32_t a[4], bf[2];
                ldm_x4(a, aA + k * 32);
                ldm_x2t(bf, bA + k * 2304);
                mma16816(d, a, bf);
            }
            int r = mt * 16 + (lane >> 2), c = nt * 8 + (lane & 3) * 2;
            sth2(sm, SM_P + r * 144 + c * 2, d[0], d[1]);
            sth2(sm, SM_P + (r + 8) * 144 + c * 2, d[2], d[3]);
        }
        __syncthreads();

        if (layer == 0) {
            // ---- node0 = P @ x0 ; +resid -> x1 into SM_Y ----
            int mt = warp >> 3, nc = warp & 7;
            float d[8] = {0.f, 0.f, 0.f, 0.f, 0.f, 0.f, 0.f, 0.f};
            uint32_t aA = sbase + SM_P + (mt * 16 + (lane & 15)) * 144 + (lane >> 4) * 16;
            uint32_t bA = sbase + SM_X + (lane & 15) * 272 + nc * 32 + (lane >> 4) * 16;
            #pragma unroll
            for (int k = 0; k < 4; k++) {
                uint32_t a[4], bf[4];
                ldm_x4(a, aA + k * 32);
                ldm_x4t(bf, bA + k * 4352);
                mma16816(d, a, bf);
                mma16816(d + 4, a, bf + 2);
            }
            int r = mt * 16 + (lane >> 2);
            #pragma unroll
            for (int t = 0; t < 2; t++) {
                int c = nc * 16 + t * 8 + (lane & 3) * 2;
                sth2(sm, SM_Y + r * 272 + c * 2,
                     d[t*4+0] + resid[r * 128 + c], d[t*4+1] + resid[r * 128 + c + 1]);
                sth2(sm, SM_Y + (r + 8) * 272 + c * 2,
                     d[t*4+2] + resid[(r + 8) * 128 + c], d[t*4+3] + resid[(r + 8) * 128 + c + 1]);
            }
            __syncthreads();
        } else {
            // ---- FUSED: copy g2w fp16 image -> base 0, AND y = P1 @ x1 -> SM_X ----
            {
                const float4* src = (const float4*)g_w2img;
                float4* dst = (float4*)(sm + SM_G2W);
                for (int i = tid; i < 2176; i += 1024) dst[i] = src[i];
            }
            {
                int mt = warp >> 3, nc = warp & 7;
                float d[8] = {0.f, 0.f, 0.f, 0.f, 0.f, 0.f, 0.f, 0.f};
                uint32_t aA = sbase + SM_P + (mt * 16 + (lane & 15)) * 144 + (lane >> 4) * 16;
                uint32_t bA = sbase + SM_Y + (lane & 15) * 272 + nc * 32 + (lane >> 4) * 16;
                #pragma unroll
                for (int k = 0; k < 4; k++) {
                    uint32_t a[4], bf[4];
                    ldm_x4(a, aA + k * 32);
                    ldm_x4t(bf, bA + k * 4352);
                    mma16816(d, a, bf);
                    mma16816(d + 4, a, bf + 2);
                }
                int r = mt * 16 + (lane >> 2);
                #pragma unroll
                for (int t = 0; t < 2; t++) {
                    int c = nc * 16 + t * 8 + (lane & 3) * 2;
                    sth2(sm, SM_X + r * 272 + c * 2, d[t*4+0], d[t*4+1]);
                    sth2(sm, SM_X + (r + 8) * 272 + c * 2, d[t*4+2], d[t*4+3]);
                }
            }
            __syncthreads();
            // ---- node1 = y @ g2w ; epilogue writes out directly (+resid) ----
            {
                int mt = warp >> 3, nc = warp & 7;
                float d[8] = {0.f, 0.f, 0.f, 0.f, 0.f, 0.f, 0.f, 0.f};
                uint32_t aA = sbase + SM_X + (mt * 16 + (lane & 15)) * 272 + (lane >> 4) * 16;
                uint32_t bA = sbase + SM_G2W + (lane & 15) * 272 + nc * 32 + (lane >> 4) * 16;
                #pragma unroll
                for (int k = 0; k < 8; k++) {
                    uint32_t a[4], bf[4];
                    ldm_x4(a, aA + k * 32);
                    ldm_x4t(bf, bA + k * 4352);
                    mma16816(d, a, bf);
                    mma16816(d + 4, a, bf + 2);
                }
                int r = mt * 16 + (lane >> 2);
                #pragma unroll
                for (int t = 0; t < 2; t++) {
                    int c = nc * 16 + t * 8 + (lane & 3) * 2;
                    float2 v0 = make_float2(d[t*4+0] + resid[r * 128 + c],
                                            d[t*4+1] + resid[r * 128 + c + 1]);
                    float2 v1 = make_float2(d[t*4+2] + resid[(r + 8) * 128 + c],
                                            d[t*4+3] + resid[(r + 8) * 128 + c + 1]);
                    size_t o0 = ((size_t)b * 64 + r) * 128 + c;
                    size_t o1 = ((size_t)b * 64 + r + 8) * 128 + c;
                    *(float2*)(out + o0) = v0;
                    *(float2*)(out + BLD + o0) = v0;
                    *(float2*)(out + o1) = v1;
                    *(float2*)(out + BLD + o1) = v1;
                }
            }
        }
    }
}

extern "C" void kernel_launch(void* const* d_in, const int* in_sizes, int n_in,
                              void* d_out, int out_size)
{
    const int*   inputs = (const int*)d_in[0];
    const float* HT     = (const float*)d_in[1];
    const float* emb    = (const float*)d_in[4];
    const float* emb2   = (const float*)d_in[5];
    const float* g1_w2  = (const float*)d_in[6];
    const float* g1_w3  = (const float*)d_in[7];
    const float* g1_q   = (const float*)d_in[8];
    const float* g1_a   = (const float*)d_in[9];
    const float* g1_a2  = (const float*)d_in[10];
    const float* g2_w   = (const float*)d_in[11];
    const float* g2_w2  = (const float*)d_in[12];
    const float* g2_w3  = (const float*)d_in[13];
    const float* g2_q   = (const float*)d_in[14];
    const float* g2_a   = (const float*)d_in[15];
    const float* g2_a2  = (const float*)d_in[16];
    float* out = (float*)d_out;

    cudaFuncSetAttribute(session_kernel,
                         cudaFuncAttributeMaxDynamicSharedMemorySize, SMEM_BYTES);

    precompute_kernel<<<dim3(2, 128), 128>>>(g1_w2, g1_w3, g1_q, g1_a, g1_a2,
                                             g2_w2, g2_w3, g2_q, g2_a, g2_a2);
    img_kernel<<<64, 256>>>(g2_w);
    session_kernel<<<Bb, 1024, SMEM_BYTES>>>(inputs, HT, emb, emb2, out);
}

// round 17
// speedup vs baseline: 1.3040x; 1.1800x over previous
#include <cuda_runtime.h>
#include <cuda_fp16.h>
#include <cstdint>

#define FULL 0xFFFFFFFFu
constexpr int Bb = 512;
constexpr float ALPHA = 0.2f;

// ---------------- mma / ldmatrix helpers ----------------
__device__ __forceinline__ void mma16816(float* d, const uint32_t* a, const uint32_t* b) {
    asm volatile("mma.sync.aligned.m16n8k16.row.col.f32.f16.f16.f32 "
        "{%0,%1,%2,%3}, {%4,%5,%6,%7}, {%8,%9}, {%0,%1,%2,%3};"
        : "+f"(d[0]), "+f"(d[1]), "+f"(d[2]), "+f"(d[3])
        : "r"(a[0]), "r"(a[1]), "r"(a[2]), "r"(a[3]), "r"(b[0]), "r"(b[1]));
}
__device__ __forceinline__ void ldm_x4(uint32_t* r, uint32_t addr) {
    asm volatile("ldmatrix.sync.aligned.m8n8.x4.shared.b16 {%0,%1,%2,%3}, [%4];"
        : "=r"(r[0]), "=r"(r[1]), "=r"(r[2]), "=r"(r[3]) : "r"(addr));
}
__device__ __forceinline__ void ldm_x4t(uint32_t* r, uint32_t addr) {
    asm volatile("ldmatrix.sync.aligned.m8n8.x4.trans.shared.b16 {%0,%1,%2,%3}, [%4];"
        : "=r"(r[0]), "=r"(r[1]), "=r"(r[2]), "=r"(r[3]) : "r"(addr));
}
__device__ __forceinline__ uint32_t smem_u32(const void* p) {
    uint32_t a;
    asm("{ .reg .u64 t; cvta.to.shared.u64 t, %1; cvt.u32.u64 %0, t; }" : "=r"(a) : "l"(p));
    return a;
}

#define RADD(v) { _Pragma("unroll") for (int _o = 16; _o; _o >>= 1) v += __shfl_xor_sync(FULL, v, _o); }

// ---------------- precomputed globals ----------------
__device__ float g_u[6][128];
__device__ float g_u3b[128];
__device__ float g_c1[2];
__device__ __align__(16) uint8_t g_w2img[34816];  // fp16 g2w [128][136]

__global__ void precompute_kernel(
    const float* __restrict__ w2a, const float* __restrict__ w3a,
    const float* __restrict__ qa,  const float* __restrict__ aa,
    const float* __restrict__ a2a,
    const float* __restrict__ w2b, const float* __restrict__ w3b,
    const float* __restrict__ qb,  const float* __restrict__ ab,
    const float* __restrict__ a2b)
{
    const int layer = blockIdx.x;
    const int k     = blockIdx.y;
    const int c     = threadIdx.x;
    const int wp    = c >> 5, ln = c & 31;
    const float* w2 = layer ? w2b : w2a;
    const float* w3 = layer ? w3b : w3a;
    const float* q  = layer ? qb  : qa;
    const float* a  = layer ? ab  : aa;
    const float* a2 = layer ? a2b : a2a;

    float w2v = w2[k * 128 + c];
    float p1 = w2v * a[128 + c];
    float p2 = w2v * a2[c];
    float p3 = w3[k * 128 + c] * a2[128 + c];
    float p4 = (k == 0) ? q[c] * a[c] : 0.f;
    RADD(p1); RADD(p2); RADD(p3); RADD(p4);
    __shared__ float sh[4][4];
    if (ln == 0) { sh[0][wp] = p1; sh[1][wp] = p2; sh[2][wp] = p3; sh[3][wp] = p4; }
    __syncthreads();
    if (c == 0) {
        float u1 = sh[0][0] + sh[0][1] + sh[0][2] + sh[0][3];
        float u2 = sh[1][0] + sh[1][1] + sh[1][2] + sh[1][3];
        float u3 = sh[2][0] + sh[2][1] + sh[2][2] + sh[2][3];
        if (layer == 0) { g_u[0][k] = u1; g_u[1][k] = u2; g_u[2][k] = u3; }
        else            { g_u[3][k] = u1; g_u[4][k] = u2; g_u3b[k] = u3; }
        if (k == 0) g_c1[layer] = sh[3][0] + sh[3][1] + sh[3][2] + sh[3][3];
    }
}

__global__ void img_kernel(const float* __restrict__ g2w) {
    int idx = blockIdx.x * 256 + threadIdx.x;
    int kk = idx >> 7, d = idx & 127;
    *(__half*)(g_w2img + (kk * 136 + d) * 2) = __float2half(g2w[kk * 128 + d]);
    int gw = blockIdx.x * 8 + (threadIdx.x >> 5);
    if (gw < 128) {
        int ln = threadIdx.x & 31;
        float s = 0.f;
        #pragma unroll
        for (int t = 0; t < 4; t++)
            s += g2w[gw * 128 + ln + 32 * t] * g_u3b[ln + 32 * t];
        RADD(s);
        if (ln == 0) g_u[5][gw] = s;
    }
}

// ---------------- smem layout (bytes); 102912 total -> 2 CTAs/SM ----------------
constexpr int SM_ATT1  = 0;        // [128][72] = 18432
constexpr int SM_ATTN  = 18432;    // [64][136] = 17408
constexpr int SM_G2W   = 0;        // 34816 overlay (layer1 after P1)
constexpr int SM_X     = 35840;    // [64][136] x0 fp16 (also serves as residual)
constexpr int SM_Y     = 53248;    // [64][136] x1
constexpr int SM_Y2    = 70656;    // [64][136] y
constexpr int SM_P     = 88064;    // [64][72] = 9216
constexpr int SM_E1V   = 97280;
constexpr int SM_S2    = 97536;
constexpr int SM_VV    = 97792;
constexpr int SM_DXA   = 98048;
constexpr int SM_DXB   = 98304;
constexpr int SM_DXC   = 98560;
constexpr int SM_F2    = 98816;    // 512
constexpr int SM_DEA   = 99328;
constexpr int SM_DEB   = 99840;
constexpr int SM_DEC   = 100352;
constexpr int SM_EMASK = 100864;   // 128 u64
constexpr int SM_NMASK = 101888;   // 128 u64
constexpr int SMEM_BYTES = 102912;

__device__ __forceinline__ void sth2(uint8_t* sm, int off, float a, float b) {
    *(__half2*)(sm + off) = __floats2half2_rn(a, b);
}
__device__ __forceinline__ float2 ldh2(const uint8_t* sm, int off) {
    return __half22float2(*(const __half2*)(sm + off));
}

__global__ __launch_bounds__(512, 2) void session_kernel(
    const int*   __restrict__ inputs,
    const float* __restrict__ HT,
    const float* __restrict__ emb,
    const float* __restrict__ emb2,
    float*       __restrict__ out)
{
    extern __shared__ __align__(16) uint8_t sm[];
    const int tid  = threadIdx.x;
    const int warp = tid >> 5;     // 0..15
    const int lane = tid & 31;
    const int l2   = 2 * lane;
    const int b    = blockIdx.x;
    const size_t BLD = (size_t)Bb * 64 * 128;
    uint32_t sbase = smem_u32(sm);

    float* e1v = (float*)(sm + SM_E1V);
    float* s2v = (float*)(sm + SM_S2);
    float* vv  = (float*)(sm + SM_VV);
    float* dxa = (float*)(sm + SM_DXA);
    float* dxb = (float*)(sm + SM_DXB);
    float* dxc = (float*)(sm + SM_DXC);
    float* f2  = (float*)(sm + SM_F2);
    float* dea = (float*)(sm + SM_DEA);
    float* deb = (float*)(sm + SM_DEB);
    float* dec = (float*)(sm + SM_DEC);
    unsigned long long* emask = (unsigned long long*)(sm + SM_EMASK);
    unsigned long long* nmask = (unsigned long long*)(sm + SM_NMASK);

    // ---- Phase 0: gathers, x0 fp16 image (= residual), 6-channel dots, masks ----
    #pragma unroll
    for (int it = 0; it < 4; it++) {
        int j = warp + 16 * it;
        int tok = inputs[b * 64 + j];
        float4 v = ((const float4*)(emb + (size_t)tok * 128))[lane];
        float4 v2 = ((const float4*)(emb2 + (size_t)tok * 128))[lane];
        ((float4*)(out + 2 * BLD + ((size_t)b * 64 + j) * 128))[lane] = v2;
        {
            __half2 h0 = __floats2half2_rn(v.x, v.y);
            __half2 h1 = __floats2half2_rn(v.z, v.w);
            uint2 pk = make_uint2(*(uint32_t*)&h0, *(uint32_t*)&h1);
            *(uint2*)(sm + SM_X + j * 272 + 8 * lane) = pk;
        }
        float p[6];
        #pragma unroll
        for (int c = 0; c < 6; c++) {
            float4 gu = ((const float4*)g_u[c])[lane];
            p[c] = v.x * gu.x + v.y * gu.y + v.z * gu.z + v.w * gu.w;
        }
        #pragma unroll
        for (int c = 0; c < 6; c++) RADD(p[c]);
        if (lane == 0) {
            float e = g_c1[0] + p[0];
            e1v[j] = e > 0.f ? e : ALPHA * e;
            s2v[j] = p[1]; vv[j] = p[2];
            dxa[j] = p[3]; dxb[j] = p[4]; dxc[j] = p[5];
        }
    }
    #pragma unroll
    for (int it = 0; it < 8; it++) {
        int e = warp + 16 * it;
        const float* row = HT + ((size_t)b * 128 + e) * 64;
        unsigned lo = __ballot_sync(FULL, row[lane] > 0.f);
        unsigned hi = __ballot_sync(FULL, row[lane + 32] > 0.f);
        if (lane == 0) emask[e] = (unsigned long long)lo | ((unsigned long long)hi << 32);
    }
    __syncthreads();
    // nmask via ballot-transpose: each warp builds 4 nodes
    {
        unsigned long long eA = emask[lane],      eB = emask[lane + 32];
        unsigned long long eC = emask[lane + 64], eD = emask[lane + 96];
        #pragma unroll
        for (int t = 0; t < 4; t++) {
            int j = warp + 16 * t;
            unsigned b0 = __ballot_sync(FULL, (eA >> j) & 1ull);
            unsigned b1 = __ballot_sync(FULL, (eB >> j) & 1ull);
            unsigned b2 = __ballot_sync(FULL, (eC >> j) & 1ull);
            unsigned b3 = __ballot_sync(FULL, (eD >> j) & 1ull);
            if (lane == 0) {
                nmask[2 * j]     = (unsigned long long)b0 | ((unsigned long long)b1 << 32);
                nmask[2 * j + 1] = (unsigned long long)b2 | ((unsigned long long)b3 << 32);
            }
        }
    }
    __syncthreads();

    for (int layer = 0; layer < 2; layer++) {
        // ---- att1[e][j] softmax: paired lanes, half2 stores ----
        {
            float ex0 = __expf(e1v[l2]), ex1 = __expf(e1v[l2 + 1]);
            float vv0 = vv[l2], vv1 = vv[l2 + 1];
            float da0 = 0.f, da1 = 0.f, db0 = 0.f, db1 = 0.f, dc0 = 0.f, dc1 = 0.f;
            if (layer == 0) {
                da0 = dxa[l2]; da1 = dxa[l2 + 1];
                db0 = dxb[l2]; db1 = dxb[l2 + 1];
                dc0 = dxc[l2]; dc1 = dxc[l2 + 1];
            }
            #pragma unroll
            for (int it = 0; it < 8; it++) {
                int e = warp + 16 * it;
                unsigned long long m = emask[e];
                bool b0 = (m >> l2) & 1ull, b1 = (m >> (l2 + 1)) & 1ull;
                float w0 = (m == 0ull) ? (1.f / 64.f) : (b0 ? ex0 : 0.f);
                float w1 = (m == 0ull) ? (1.f / 64.f) : (b1 ? ex1 : 0.f);
                float s = w0 + w1;
                float t = w0 * vv0 + w1 * vv1;
                float ta = 0.f, tb = 0.f, tc = 0.f;
                if (layer == 0) {
                    ta = w0 * da0 + w1 * da1;
                    tb = w0 * db0 + w1 * db1;
                    tc = w0 * dc0 + w1 * dc1;
                }
                RADD(s); RADD(t);
                if (layer == 0) { RADD(ta); RADD(tb); RADD(tc); }
                float inv = 1.f / s;
                if (lane == 0) {
                    f2[e] = t * inv;
                    if (layer == 0) { dea[e] = ta * inv; deb[e] = tb * inv; dec[e] = tc * inv; }
                }
                sth2(sm, SM_ATT1 + e * 144 + 4 * lane, w0 * inv, w1 * inv);
            }
        }
        __syncthreads();

        // ---- attN[j][e] softmax: paired lanes ----
        {
            float f2l[4], efv[4], ef02v[4];
            #pragma unroll
            for (int t = 0; t < 4; t++) {
                int ei = (t >> 1) * 64 + l2 + (t & 1);
                float f = f2[ei];
                f2l[t] = f;
                efv[t] = __expf(f);
                ef02v[t] = __expf(ALPHA * f);
            }
            #pragma unroll
            for (int it = 0; it < 4; it++) {
                int j = warp + 16 * it;
                unsigned long long m0 = nmask[2 * j], m1 = nmask[2 * j + 1];
                float ss = s2v[j];
                float esj = __expf(ss), es02j = __expf(ALPHA * ss);
                bool empty = (m0 | m1) == 0ull;
                bool bt[4] = { (bool)((m0 >> l2) & 1ull), (bool)((m0 >> (l2 + 1)) & 1ull),
                               (bool)((m1 >> l2) & 1ull), (bool)((m1 >> (l2 + 1)) & 1ull) };
                float w[4];
                float s = 0.f;
                #pragma unroll
                for (int t = 0; t < 4; t++) {
                    float val = (ss + f2l[t] > 0.f) ? esj * efv[t] : es02j * ef02v[t];
                    w[t] = empty ? (1.f / 128.f) : (bt[t] ? val : 0.f);
                    s += w[t];
                }
                float ta = 0.f, tb = 0.f, tc = 0.f;
                if (layer == 0) {
                    #pragma unroll
                    for (int t = 0; t < 4; t++) {
                        int ei = (t >> 1) * 64 + l2 + (t & 1);
                        ta += w[t] * dea[ei];
                        tb += w[t] * deb[ei];
                        tc += w[t] * dec[ei];
                    }
                }
                RADD(s);
                if (layer == 0) { RADD(ta); RADD(tb); RADD(tc); }
                float inv = 1.f / s;
                if (layer == 0 && lane == 0) {
                    float x1a = g_c1[1] + ta * inv + dxa[j];
                    e1v[j] = x1a > 0.f ? x1a : ALPHA * x1a;
                    s2v[j] = tb * inv + dxb[j];
                    vv[j]  = tc * inv + dxc[j];
                }
                sth2(sm, SM_ATTN + j * 272 + 4 * lane, w[0] * inv, w[1] * inv);
                sth2(sm, SM_ATTN + j * 272 + 128 + 4 * lane, w[2] * inv, w[3] * inv);
            }
        }
        __syncthreads();

        // ---- P = attN @ att1 : M64 K128 N64 ; 16 warps = 4 mt x 4 nt2(16 cols) ----
        {
            int mt = warp >> 2, nt2 = warp & 3;
            float d[8] = {0.f, 0.f, 0.f, 0.f, 0.f, 0.f, 0.f, 0.f};
            uint32_t aA = sbase + SM_ATTN + (mt * 16 + (lane & 15)) * 272 + (lane >> 4) * 16;
            uint32_t bA = sbase + SM_ATT1 + (lane & 15) * 144 + nt2 * 32 + (lane >> 4) * 16;
            #pragma unroll
            for (int k = 0; k < 8; k++) {
                uint32_t a[4], bf[4];
                ldm_x4(a, aA + k * 32);
                ldm_x4t(bf, bA + k * 2304);
                mma16816(d, a, bf);
                mma16816(d + 4, a, bf + 2);
            }
            int r = mt * 16 + (lane >> 2);
            #pragma unroll
            for (int t = 0; t < 2; t++) {
                int c = nt2 * 16 + t * 8 + (lane & 3) * 2;
                sth2(sm, SM_P + r * 144 + c * 2, d[t*4+0], d[t*4+1]);
                sth2(sm, SM_P + (r + 8) * 144 + c * 2, d[t*4+2], d[t*4+3]);
            }
        }
        __syncthreads();

        if (layer == 0) {
            // ---- node0 = P @ x0 ; +resid(from SM_X fp16) -> x1 into SM_Y ----
            int mt = warp >> 2, nc = warp & 3;
            float d[16];
            #pragma unroll
            for (int i = 0; i < 16; i++) d[i] = 0.f;
            uint32_t aA = sbase + SM_P + (mt * 16 + (lane & 15)) * 144 + (lane >> 4) * 16;
            uint32_t bA = sbase + SM_X + (lane & 15) * 272 + nc * 64 + (lane >> 4) * 16;
            #pragma unroll
            for (int k = 0; k < 4; k++) {
                uint32_t a[4], bf[8];
                ldm_x4(a, aA + k * 32);
                ldm_x4t(bf, bA + k * 4352);
                ldm_x4t(bf + 4, bA + 32 + k * 4352);
                mma16816(d, a, bf);
                mma16816(d + 4, a, bf + 2);
                mma16816(d + 8, a, bf + 4);
                mma16816(d + 12, a, bf + 6);
            }
            int r = mt * 16 + (lane >> 2);
            #pragma unroll
            for (int t = 0; t < 4; t++) {
                int c = nc * 32 + t * 8 + (lane & 3) * 2;
                float2 r0 = ldh2(sm, SM_X + r * 272 + c * 2);
                float2 r1 = ldh2(sm, SM_X + (r + 8) * 272 + c * 2);
                sth2(sm, SM_Y + r * 272 + c * 2, d[t*4+0] + r0.x, d[t*4+1] + r0.y);
                sth2(sm, SM_Y + (r + 8) * 272 + c * 2, d[t*4+2] + r1.x, d[t*4+3] + r1.y);
            }
            __syncthreads();
        } else {
            // ---- FUSED: copy g2w fp16 image -> base 0, AND y = P1 @ x1 -> SM_Y2 ----
            {
                const float4* src = (const float4*)g_w2img;
                float4* dst = (float4*)(sm + SM_G2W);
                for (int i = tid; i < 2176; i += 512) dst[i] = src[i];
            }
            {
                int mt = warp >> 2, nc = warp & 3;
                float d[16];
                #pragma unroll
                for (int i = 0; i < 16; i++) d[i] = 0.f;
                uint32_t aA = sbase + SM_P + (mt * 16 + (lane & 15)) * 144 + (lane >> 4) * 16;
                uint32_t bA = sbase + SM_Y + (lane & 15) * 272 + nc * 64 + (lane >> 4) * 16;
                #pragma unroll
                for (int k = 0; k < 4; k++) {
                    uint32_t a[4], bf[8];
                    ldm_x4(a, aA + k * 32);
                    ldm_x4t(bf, bA + k * 4352);
                    ldm_x4t(bf + 4, bA + 32 + k * 4352);
                    mma16816(d, a, bf);
                    mma16816(d + 4, a, bf + 2);
                    mma16816(d + 8, a, bf + 4);
                    mma16816(d + 12, a, bf + 6);
                }
                int r = mt * 16 + (lane >> 2);
                #pragma unroll
                for (int t = 0; t < 4; t++) {
                    int c = nc * 32 + t * 8 + (lane & 3) * 2;
                    sth2(sm, SM_Y2 + r * 272 + c * 2, d[t*4+0], d[t*4+1]);
                    sth2(sm, SM_Y2 + (r + 8) * 272 + c * 2, d[t*4+2], d[t*4+3]);
                }
            }
            __syncthreads();
            // ---- node1 = y @ g2w ; +resid(SM_X) -> out directly ----
            {
                int mt = warp >> 2, nc = warp & 3;
                float d[16];
                #pragma unroll
                for (int i = 0; i < 16; i++) d[i] = 0.f;
                uint32_t aA = sbase + SM_Y2 + (mt * 16 + (lane & 15)) * 272 + (lane >> 4) * 16;
                uint32_t bA = sbase + SM_G2W + (lane & 15) * 272 + nc * 64 + (lane >> 4) * 16;
                #pragma unroll
                for (int k = 0; k < 8; k++) {
                    uint32_t a[4], bf[8];
                    ldm_x4(a, aA + k * 32);
                    ldm_x4t(bf, bA + k * 4352);
                    ldm_x4t(bf + 4, bA + 32 + k * 4352);
                    mma16816(d, a, bf);
                    mma16816(d + 4, a, bf + 2);
                    mma16816(d + 8, a, bf + 4);
                    mma16816(d + 12, a, bf + 6);
                }
                int r = mt * 16 + (lane >> 2);
                #pragma unroll
                for (int t = 0; t < 4; t++) {
                    int c = nc * 32 + t * 8 + (lane & 3) * 2;
                    float2 r0 = ldh2(sm, SM_X + r * 272 + c * 2);
                    float2 r1 = ldh2(sm, SM_X + (r + 8) * 272 + c * 2);
                    float2 v0 = make_float2(d[t*4+0] + r0.x, d[t*4+1] + r0.y);
                    float2 v1 = make_float2(d[t*4+2] + r1.x, d[t*4+3] + r1.y);
                    size_t o0 = ((size_t)b * 64 + r) * 128 + c;
                    size_t o1 = ((size_t)b * 64 + r + 8) * 128 + c;
                    *(float2*)(out + o0) = v0;
                    *(float2*)(out + BLD + o0) = v0;
                    *(float2*)(out + o1) = v1;
                    *(float2*)(out + BLD + o1) = v1;
                }
            }
        }
    }
}

extern "C" void kernel_launch(void* const* d_in, const int* in_sizes, int n_in,
                              void* d_out, int out_size)
{
    const int*   inputs = (const int*)d_in[0];
    const float* HT     = (const float*)d_in[1];
    const float* emb    = (const float*)d_in[4];
    const float* emb2   = (const float*)d_in[5];
    const float* g1_w2  = (const float*)d_in[6];
    const float* g1_w3  = (const float*)d_in[7];
    const float* g1_q   = (const float*)d_in[8];
    const float* g1_a   = (const float*)d_in[9];
    const float* g1_a2  = (const float*)d_in[10];
    const float* g2_w   = (const float*)d_in[11];
    const float* g2_w2  = (const float*)d_in[12];
    const float* g2_w3  = (const float*)d_in[13];
    const float* g2_q   = (const float*)d_in[14];
    const float* g2_a   = (const float*)d_in[15];
    const float* g2_a2  = (const float*)d_in[16];
    float* out = (float*)d_out;

    cudaFuncSetAttribute(session_kernel,
                         cudaFuncAttributeMaxDynamicSharedMemorySize, SMEM_BYTES);

    precompute_kernel<<<dim3(2, 128), 128>>>(g1_w2, g1_w3, g1_q, g1_a, g1_a2,
                                             g2_w2, g2_w3, g2_q, g2_a, g2_a2);
    img_kernel<<<64, 256>>>(g2_w);
    session_kernel<<<Bb, 512, SMEM_BYTES>>>(inputs, HT, emb, emb2, out);
}